// round 1
// baseline (speedup 1.0000x reference)
#include <cuda_runtime.h>
#include <cstdint>

// Problem constants
#define B_    32
#define CIN_  256
#define COUT_ 256
#define H_    56
#define W_    56
#define KEXP_ 4
#define HW_   (H_ * W_)          // 3136
#define KDIM_ (CIN_ * 9)         // 2304 (implicit-GEMM K)
#define WPE_  (COUT_ * CIN_ * 9) // 589824 weight elems per expert

// Scratch (allocation-free rule: __device__ globals)
__device__ float g_pooled[B_ * CIN_];
__device__ float g_att[B_ * KEXP_];
__device__ float g_aggw[(size_t)B_ * WPE_];   // 75.5 MB

// ---------------------------------------------------------------------------
// Kernel 1: global average pool  pooled[b][c] = mean(x[b][c][:][:])
// grid (CIN, B), 256 threads
// ---------------------------------------------------------------------------
__global__ void pool_kernel(const float* __restrict__ x) {
    int c = blockIdx.x, b = blockIdx.y;
    const float4* p = (const float4*)(x + ((size_t)(b * CIN_ + c)) * HW_);
    float s = 0.f;
    for (int i = threadIdx.x; i < HW_ / 4; i += 256) {
        float4 v = p[i];
        s += (v.x + v.y) + (v.z + v.w);
    }
    #pragma unroll
    for (int o = 16; o > 0; o >>= 1) s += __shfl_xor_sync(0xffffffffu, s, o);
    __shared__ float sm[8];
    if ((threadIdx.x & 31) == 0) sm[threadIdx.x >> 5] = s;
    __syncthreads();
    if (threadIdx.x == 0) {
        float v = 0.f;
        #pragma unroll
        for (int i = 0; i < 8; i++) v += sm[i];
        g_pooled[b * CIN_ + c] = v * (1.f / (float)HW_);
    }
}

// ---------------------------------------------------------------------------
// Kernel 2: attention  att[b][k] = softmax_j(relu(pooled@fc1^T+b1)@fc2^T+b2)
// 1 block, 128 threads: thread = (b, k), b = tid>>2, k = tid&3
// ---------------------------------------------------------------------------
__global__ void attn_kernel(const float* __restrict__ fc1_w,
                            const float* __restrict__ fc1_b,
                            const float* __restrict__ fc2_w,
                            const float* __restrict__ fc2_b) {
    __shared__ float a_sm[B_][KEXP_];
    __shared__ float l_sm[B_][KEXP_];
    int tid = threadIdx.x;
    int b = tid >> 2, k = tid & 3;

    float s = 0.f;
    const float* pb = g_pooled + b * CIN_;
    const float* wk = fc1_w + k * CIN_;
    for (int c = 0; c < CIN_; c++) s += pb[c] * wk[c];
    s += fc1_b[k];
    a_sm[b][k] = fmaxf(s, 0.f);
    __syncthreads();

    int j = k;
    float l = fc2_b[j];
    #pragma unroll
    for (int kk = 0; kk < KEXP_; kk++) l += a_sm[b][kk] * fc2_w[j * KEXP_ + kk];
    l_sm[b][j] = l;
    __syncthreads();

    float m = fmaxf(fmaxf(l_sm[b][0], l_sm[b][1]), fmaxf(l_sm[b][2], l_sm[b][3]));
    float e = expf(l_sm[b][j] - m);
    float sum = expf(l_sm[b][0] - m) + expf(l_sm[b][1] - m) +
                expf(l_sm[b][2] - m) + expf(l_sm[b][3] - m);
    g_att[b * KEXP_ + j] = e / sum;
}

// ---------------------------------------------------------------------------
// Kernel 3: weight aggregation  agg_w[b] = sum_k att[b][k] * weight[k]
// grid (WPE_/4/256 = 576, B), 256 threads, float4 streaming
// ---------------------------------------------------------------------------
__global__ void aggw_kernel(const float* __restrict__ weight) {
    int b = blockIdx.y;
    int j = blockIdx.x * 256 + threadIdx.x;   // float4 index, 147456 per b
    float a0 = g_att[b * 4 + 0], a1 = g_att[b * 4 + 1];
    float a2 = g_att[b * 4 + 2], a3 = g_att[b * 4 + 3];
    const float4* w = (const float4*)weight;
    const int Q = WPE_ / 4;                   // 147456
    float4 w0 = w[0 * Q + j], w1 = w[1 * Q + j], w2 = w[2 * Q + j], w3 = w[3 * Q + j];
    float4 r;
    r.x = a0 * w0.x + a1 * w1.x + a2 * w2.x + a3 * w3.x;
    r.y = a0 * w0.y + a1 * w1.y + a2 * w2.y + a3 * w3.y;
    r.z = a0 * w0.z + a1 * w1.z + a2 * w2.z + a3 * w3.z;
    r.w = a0 * w0.w + a1 * w1.w + a2 * w2.w + a3 * w3.w;
    ((float4*)g_aggw)[(size_t)b * Q + j] = r;
}

// ---------------------------------------------------------------------------
// Kernel 4: per-sample implicit-GEMM conv
// C[co, p] = sum_k A[co, k] * B[k, p] + agg_bias[co]
//   A = agg_w[b]  [256 x 2304]  (row-major, k = ci*9 + kh*3 + kw)
//   B = im2col(x[b])  [2304 x 3136]
// BM=BN=128, BK=8, 256 threads, 8x8 micro-tile per thread
// grid (ceil(3136/128)=25, 2, 32)
// ---------------------------------------------------------------------------
#define BM 128
#define BN 128
#define BK 8

__global__ __launch_bounds__(256, 2)
void conv_kernel(const float* __restrict__ x,
                 const float* __restrict__ bias,
                 float* __restrict__ out) {
    __shared__ float As[BK][BM];
    __shared__ float Bs[BK][BN];
    __shared__ float bsm[BM];

    int b      = blockIdx.z;
    int coBase = blockIdx.y * BM;
    int pBase  = blockIdx.x * BN;
    int tid    = threadIdx.x;
    int tx     = tid & 15;     // 0..15 -> pixel cols (8 each)
    int ty     = tid >> 4;     // 0..15 -> co rows   (8 each)

    // aggregated bias for this co tile
    if (tid < BM) {
        float a0 = g_att[b * 4 + 0], a1 = g_att[b * 4 + 1];
        float a2 = g_att[b * 4 + 2], a3 = g_att[b * 4 + 3];
        int co = coBase + tid;
        bsm[tid] = a0 * bias[0 * COUT_ + co] + a1 * bias[1 * COUT_ + co] +
                   a2 * bias[2 * COUT_ + co] + a3 * bias[3 * COUT_ + co];
    }

    float acc[8][8];
    #pragma unroll
    for (int i = 0; i < 8; i++)
        #pragma unroll
        for (int j = 0; j < 8; j++) acc[i][j] = 0.f;

    const float* Ag = g_aggw + ((size_t)b * COUT_ + coBase) * KDIM_;
    const float* xg = x + (size_t)b * CIN_ * HW_;

    int am = tid >> 1;            // 0..127 (co row within tile)
    int ak = (tid & 1) * 4;       // 0 or 4 (k sub-offset)

    for (int k0 = 0; k0 < KDIM_; k0 += BK) {
        // ---- gmem loads to registers ----
        float4 av = *(const float4*)(Ag + (size_t)am * KDIM_ + k0 + ak);

        float bv[4];
        #pragma unroll
        for (int i = 0; i < 4; i++) {
            int e  = tid + i * 256;          // 0..1023
            int kk = e >> 7;                 // 0..7
            int pp = e & 127;                // 0..127
            int k  = k0 + kk;
            int ci  = k / 9;
            int rem = k - ci * 9;
            int kh  = rem / 3;
            int kw  = rem - kh * 3;
            int p = pBase + pp;
            float v = 0.f;
            if (p < HW_) {
                int oh = p / W_, ow = p - oh * W_;
                int ih = oh + kh - 1, iw = ow + kw - 1;
                if ((unsigned)ih < (unsigned)H_ && (unsigned)iw < (unsigned)W_)
                    v = xg[(size_t)ci * HW_ + ih * W_ + iw];
            }
            bv[i] = v;
        }

        __syncthreads();   // previous tile's compute done

        // ---- stage to smem ----
        As[ak + 0][am] = av.x;
        As[ak + 1][am] = av.y;
        As[ak + 2][am] = av.z;
        As[ak + 3][am] = av.w;
        #pragma unroll
        for (int i = 0; i < 4; i++) {
            int e  = tid + i * 256;
            int kk = e >> 7;
            int pp = e & 127;
            Bs[kk][pp] = bv[i];
        }

        __syncthreads();

        // ---- compute ----
        #pragma unroll
        for (int r = 0; r < BK; r++) {
            float4 a0 = *(const float4*)&As[r][ty * 8];
            float4 a1 = *(const float4*)&As[r][ty * 8 + 4];
            float4 b0 = *(const float4*)&Bs[r][tx * 8];
            float4 b1 = *(const float4*)&Bs[r][tx * 8 + 4];
            float aa[8] = {a0.x, a0.y, a0.z, a0.w, a1.x, a1.y, a1.z, a1.w};
            float bb[8] = {b0.x, b0.y, b0.z, b0.w, b1.x, b1.y, b1.z, b1.w};
            #pragma unroll
            for (int i = 0; i < 8; i++)
                #pragma unroll
                for (int j = 0; j < 8; j++)
                    acc[i][j] += aa[i] * bb[j];
        }
    }

    // ---- epilogue: add bias, store ----
    #pragma unroll
    for (int i = 0; i < 8; i++) {
        int co = coBase + ty * 8 + i;
        float bb = bsm[ty * 8 + i];
        float* orow = out + ((size_t)(b * COUT_ + co)) * HW_;
        #pragma unroll
        for (int j4 = 0; j4 < 2; j4++) {
            int p = pBase + tx * 8 + j4 * 4;
            if (p < HW_) {
                float4 v;
                v.x = acc[i][j4 * 4 + 0] + bb;
                v.y = acc[i][j4 * 4 + 1] + bb;
                v.z = acc[i][j4 * 4 + 2] + bb;
                v.w = acc[i][j4 * 4 + 3] + bb;
                *(float4*)(orow + p) = v;
            }
        }
    }
}

// ---------------------------------------------------------------------------
// launch
// inputs: 0=x 1=weight 2=bias 3=fc1_w 4=fc1_b 5=fc2_w 6=fc2_b
// ---------------------------------------------------------------------------
extern "C" void kernel_launch(void* const* d_in, const int* in_sizes, int n_in,
                              void* d_out, int out_size) {
    const float* x      = (const float*)d_in[0];
    const float* weight = (const float*)d_in[1];
    const float* bias   = (const float*)d_in[2];
    const float* fc1_w  = (const float*)d_in[3];
    const float* fc1_b  = (const float*)d_in[4];
    const float* fc2_w  = (const float*)d_in[5];
    const float* fc2_b  = (const float*)d_in[6];
    float* out = (float*)d_out;

    pool_kernel<<<dim3(CIN_, B_), 256>>>(x);
    attn_kernel<<<1, 128>>>(fc1_w, fc1_b, fc2_w, fc2_b);
    aggw_kernel<<<dim3(WPE_ / 4 / 256, B_), 256>>>(weight);
    conv_kernel<<<dim3((HW_ + BN - 1) / BN, COUT_ / BM, B_), 256>>>(x, bias, out);
}

// round 3
// speedup vs baseline: 2.0892x; 2.0892x over previous
#include <cuda_runtime.h>
#include <cuda_bf16.h>
#include <cstdint>

#define B_    32
#define CIN_  256
#define COUT_ 256
#define H_    56
#define W_    56
#define HW_   3136
#define KDIM_ 2304
#define WPE_  (COUT_ * CIN_ * 9)

#define BM 128
#define BN 128
#define BK 64
#define NCHUNK 36

// SMEM layout (single buffer)
#define OFF_AH 0
#define OFF_AL 16384
#define OFF_BH 32768
#define OFF_BL (49152 + 64)          // +64B so Bl stores land on disjoint banks
#define DSMEM_BYTES 66688

// A tile: 128 rows x 128B (64 bf16), SW128 swizzle
#define SW128(o) ((o) ^ (((o) >> 3) & 0x70))
// B tile: 64 k-rows x 256B (128 bf16), swizzle bits[4:6] ^= bits[8:10]
#define SWB(o)   ((o) ^ (((o) >> 4) & 0x70))

// ------------------------- scratch -------------------------
__device__ float g_pooled[B_ * CIN_];
__device__ float g_att[B_ * 4];
__device__ __align__(16) __nv_bfloat16 g_awhi[(size_t)B_ * COUT_ * KDIM_];
__device__ __align__(16) __nv_bfloat16 g_awlo[(size_t)B_ * COUT_ * KDIM_];
__device__ __align__(16) uint32_t g_xs[(size_t)B_ * CIN_ * HW_]; // hi(lo16)|lo(hi16)

// ------------------------- helpers -------------------------
__device__ __forceinline__ uint32_t smem_u32(const void* p) {
    uint32_t a;
    asm("{ .reg .u64 t; cvta.to.shared.u64 t, %1; cvt.u32.u64 %0, t; }"
        : "=r"(a) : "l"(p));
    return a;
}

__device__ __forceinline__ void split_bf16(float v, unsigned short& h, unsigned short& l) {
    __nv_bfloat16 hb = __float2bfloat16(v);
    float hf = __bfloat162float(hb);
    __nv_bfloat16 lb = __float2bfloat16(v - hf);
    h = __bfloat16_as_ushort(hb);
    l = __bfloat16_as_ushort(lb);
}

#define LDSM4(r, addr)                                                        \
    asm volatile("ldmatrix.sync.aligned.m8n8.x4.shared.b16 {%0,%1,%2,%3}, [%4];" \
        : "=r"((r)[0]), "=r"((r)[1]), "=r"((r)[2]), "=r"((r)[3]) : "r"(addr))

#define LDSM4T(r, addr)                                                       \
    asm volatile("ldmatrix.sync.aligned.m8n8.x4.trans.shared.b16 {%0,%1,%2,%3}, [%4];" \
        : "=r"((r)[0]), "=r"((r)[1]), "=r"((r)[2]), "=r"((r)[3]) : "r"(addr))

#define MMA(d, a, b0v, b1v)                                                   \
    asm volatile("mma.sync.aligned.m16n8k16.row.col.f32.bf16.bf16.f32 "       \
        "{%0,%1,%2,%3}, {%4,%5,%6,%7}, {%8,%9}, {%0,%1,%2,%3};"               \
        : "+f"((d)[0]), "+f"((d)[1]), "+f"((d)[2]), "+f"((d)[3])              \
        : "r"((a)[0]), "r"((a)[1]), "r"((a)[2]), "r"((a)[3]),                 \
          "r"(b0v), "r"(b1v))

// ------------------------- kernel 1: pool -------------------------
__global__ void pool_kernel(const float* __restrict__ x) {
    int c = blockIdx.x, b = blockIdx.y;
    const float4* p = (const float4*)(x + ((size_t)(b * CIN_ + c)) * HW_);
    float s = 0.f;
    for (int i = threadIdx.x; i < HW_ / 4; i += 256) {
        float4 v = p[i];
        s += (v.x + v.y) + (v.z + v.w);
    }
    #pragma unroll
    for (int o = 16; o > 0; o >>= 1) s += __shfl_xor_sync(0xffffffffu, s, o);
    __shared__ float sm[8];
    if ((threadIdx.x & 31) == 0) sm[threadIdx.x >> 5] = s;
    __syncthreads();
    if (threadIdx.x == 0) {
        float v = 0.f;
        #pragma unroll
        for (int i = 0; i < 8; i++) v += sm[i];
        g_pooled[b * CIN_ + c] = v * (1.f / (float)HW_);
    }
}

// ------------------------- kernel 2: attention -------------------------
__global__ void attn_kernel(const float* __restrict__ fc1_w,
                            const float* __restrict__ fc1_b,
                            const float* __restrict__ fc2_w,
                            const float* __restrict__ fc2_b) {
    __shared__ float a_sm[B_][4];
    __shared__ float l_sm[B_][4];
    int tid = threadIdx.x;
    int b = tid >> 2, k = tid & 3;

    float s = 0.f;
    const float* pb = g_pooled + b * CIN_;
    const float* wk = fc1_w + k * CIN_;
    for (int c = 0; c < CIN_; c++) s += pb[c] * wk[c];
    s += fc1_b[k];
    a_sm[b][k] = fmaxf(s, 0.f);
    __syncthreads();

    float l = fc2_b[k];
    #pragma unroll
    for (int kk = 0; kk < 4; kk++) l += a_sm[b][kk] * fc2_w[k * 4 + kk];
    l_sm[b][k] = l;
    __syncthreads();

    float m = fmaxf(fmaxf(l_sm[b][0], l_sm[b][1]), fmaxf(l_sm[b][2], l_sm[b][3]));
    float e = expf(l_sm[b][k] - m);
    float sum = expf(l_sm[b][0] - m) + expf(l_sm[b][1] - m) +
                expf(l_sm[b][2] - m) + expf(l_sm[b][3] - m);
    g_att[b * 4 + k] = e / sum;
}

// ------------------------- kernel 3: weight agg + bf16 split -------------------------
__global__ void aggw_kernel(const float* __restrict__ weight) {
    int b = blockIdx.y;
    int j = blockIdx.x * 256 + threadIdx.x;
    float a0 = g_att[b * 4 + 0], a1 = g_att[b * 4 + 1];
    float a2 = g_att[b * 4 + 2], a3 = g_att[b * 4 + 3];
    const float4* w = (const float4*)weight;
    const int Q = WPE_ / 4;
    float4 w0 = w[0 * Q + j], w1 = w[1 * Q + j], w2 = w[2 * Q + j], w3 = w[3 * Q + j];
    float v[4];
    v[0] = a0 * w0.x + a1 * w1.x + a2 * w2.x + a3 * w3.x;
    v[1] = a0 * w0.y + a1 * w1.y + a2 * w2.y + a3 * w3.y;
    v[2] = a0 * w0.z + a1 * w1.z + a2 * w2.z + a3 * w3.z;
    v[3] = a0 * w0.w + a1 * w1.w + a2 * w2.w + a3 * w3.w;
    uint32_t hi[2], lo[2];
    #pragma unroll
    for (int h = 0; h < 2; h++) {
        unsigned short h0, l0, h1, l1;
        split_bf16(v[h * 2 + 0], h0, l0);
        split_bf16(v[h * 2 + 1], h1, l1);
        hi[h] = (uint32_t)h0 | ((uint32_t)h1 << 16);
        lo[h] = (uint32_t)l0 | ((uint32_t)l1 << 16);
    }
    size_t u = (size_t)b * (WPE_ / 2) + (size_t)j * 2;
    ((uint32_t*)g_awhi)[u]     = hi[0];
    ((uint32_t*)g_awhi)[u + 1] = hi[1];
    ((uint32_t*)g_awlo)[u]     = lo[0];
    ((uint32_t*)g_awlo)[u + 1] = lo[1];
}

// ------------------------- kernel 4: x split -------------------------
__global__ void xsplit_kernel(const float* __restrict__ x) {
    size_t i4 = (size_t)blockIdx.x * 256 + threadIdx.x;
    float4 v = ((const float4*)x)[i4];
    float vv[4] = {v.x, v.y, v.z, v.w};
    uint4 o;
    unsigned short h, l;
    split_bf16(vv[0], h, l); o.x = (uint32_t)h | ((uint32_t)l << 16);
    split_bf16(vv[1], h, l); o.y = (uint32_t)h | ((uint32_t)l << 16);
    split_bf16(vv[2], h, l); o.z = (uint32_t)h | ((uint32_t)l << 16);
    split_bf16(vv[3], h, l); o.w = (uint32_t)h | ((uint32_t)l << 16);
    ((uint4*)g_xs)[i4] = o;
}

// ------------------------- kernel 5: HMMA conv -------------------------
// grid (25, 2, 32), 256 threads (8 warps: wm = wid/4 in [0,2), wn = wid%4)
// warp tile 64(m) x 32(n); mma m16n8k16; split products AhBh + AhBl + AlBh
__global__ void __launch_bounds__(256, 2)
conv_kernel(const float* __restrict__ bias, float* __restrict__ out) {
    extern __shared__ char dsm[];
    __shared__ float bsm[BM];

    int tid = threadIdx.x, wid = tid >> 5, lane = tid & 31;
    int b = blockIdx.z, coBase = blockIdx.y * BM, pBase = blockIdx.x * BN;
    int wm = wid >> 2, wn = wid & 3;

    uint32_t dbase = smem_u32(dsm);
    uint32_t abase = (dbase + 1023) & ~1023u;
    char* dp = dsm + (abase - dbase);
    char* AH = dp + OFF_AH; char* AL = dp + OFF_AL;
    char* BH = dp + OFF_BH; char* BL = dp + OFF_BL;
    uint32_t AH32 = abase + OFF_AH, AL32 = abase + OFF_AL;
    uint32_t BH32 = abase + OFF_BH, BL32 = abase + OFF_BL;

    if (tid < BM) {
        float a0 = g_att[b * 4 + 0], a1 = g_att[b * 4 + 1];
        float a2 = g_att[b * 4 + 2], a3 = g_att[b * 4 + 3];
        int co = coBase + tid;
        bsm[tid] = a0 * bias[0 * COUT_ + co] + a1 * bias[1 * COUT_ + co] +
                   a2 * bias[2 * COUT_ + co] + a3 * bias[3 * COUT_ + co];
    }

    const uint32_t* xsb = g_xs + (size_t)b * CIN_ * HW_;
    const uint4* AhiG = (const uint4*)(g_awhi + ((size_t)(b * COUT_ + coBase)) * KDIM_);
    const uint4* AloG = (const uint4*)(g_awlo + ((size_t)(b * COUT_ + coBase)) * KDIM_);

    float acc[4][4][4];
    #pragma unroll
    for (int i = 0; i < 4; i++)
        #pragma unroll
        for (int j = 0; j < 4; j++)
            #pragma unroll
            for (int q = 0; q < 4; q++) acc[i][j][q] = 0.f;

    // ldmatrix address precompute
    // A: lane -> row (lane&15), col half (lane>>4)*16B, per m-subtile
    uint32_t rA[4];
    #pragma unroll
    for (int mi = 0; mi < 4; mi++)
        rA[mi] = (uint32_t)((wm * 64 + mi * 16 + (lane & 15)) * 128 + (lane >> 4) * 16);
    // B (trans): q = lane/8: (q&1) -> k-half(+8 rows), (q>>1) -> n-half(+8 cols)
    uint32_t sB[2];
    {
        int q = lane >> 3, s = lane & 7;
        #pragma unroll
        for (int nh = 0; nh < 2; nh++) {
            uint32_t base = (uint32_t)(((q & 1) * 8 + s) * 256 +
                                       (wn * 32 + nh * 16 + (q >> 1) * 8) * 2);
            sB[nh] = SWB(base);
        }
    }

    int kloc = wid * 8;   // this warp's 8 k-rows within the chunk (B fill)

    for (int c = 0; c < NCHUNK; c++) {
        int k0 = c * BK;
        __syncthreads();   // previous compute done before overwrite

        // ---- A fill: 128 rows x 64 bf16 (hi & lo), 16B per thread-iter ----
        int kq = k0 >> 3;
        #pragma unroll
        for (int i = 0; i < 4; i++) {
            int e = i * 256 + tid;
            int m = e >> 3, j4 = e & 7;
            uint32_t off = SW128((uint32_t)(m * 128 + j4 * 16));
            *(uint4*)(AH + off) = AhiG[m * (KDIM_ / 8) + kq + j4];
            *(uint4*)(AL + off) = AloG[m * (KDIM_ / 8) + kq + j4];
        }

        // ---- B fill: k-major [64 k-rows][128 pixels], coalesced loads,
        //      shfl-paired repack into Bh / Bl ----
        #pragma unroll
        for (int kk = 0; kk < 8; kk++) {
            int k = k0 + kloc + kk;
            int ci = k / 9, rem = k - 9 * ci;
            int kh = rem / 3, kw = rem - 3 * kh;
            const uint32_t* q = xsb + (size_t)ci * HW_ + (kh - 1) * W_ + (kw - 1);
            int kb = (kloc + kk) * 256;
            int kh1 = kh - 1, kw1 = kw - 1;
            #pragma unroll
            for (int g = 0; g < 4; g++) {
                int pl = g * 32 + lane;
                int p = pBase + pl;
                int oh = p / W_, ow = p - oh * W_;
                bool ok = (p < HW_) && ((unsigned)(oh + kh1) < (unsigned)H_) &&
                          ((unsigned)(ow + kw1) < (unsigned)W_);
                uint32_t v = ok ? q[p] : 0u;
                uint32_t pv = __shfl_xor_sync(0xffffffffu, v, 1);
                bool ev = (lane & 1) == 0;
                uint32_t word = ev ? ((v & 0xFFFFu) | (pv << 16))
                                   : ((pv >> 16) | (v & 0xFFFF0000u));
                uint32_t off = SWB((uint32_t)(kb + (pl & ~1) * 2));
                *(uint32_t*)((ev ? BH : BL) + off) = word;
            }
        }

        __syncthreads();

        // ---- compute: 4 k16-steps, 3 split products each ----
        #pragma unroll
        for (int ks = 0; ks < 4; ks++) {
            uint32_t ah[4][4], al[4][4];
            #pragma unroll
            for (int mi = 0; mi < 4; mi++) {
                uint32_t offA = SW128(rA[mi] + (uint32_t)(ks * 32));
                LDSM4(ah[mi], AH32 + offA);
                LDSM4(al[mi], AL32 + offA);
            }
            #pragma unroll
            for (int nh = 0; nh < 2; nh++) {
                uint32_t bh[4], bl[4];
                uint32_t offB = sB[nh] + (uint32_t)(ks * 4096);
                LDSM4T(bh, BH32 + offB);
                LDSM4T(bl, BL32 + offB);
                #pragma unroll
                for (int mi = 0; mi < 4; mi++) {
                    #pragma unroll
                    for (int jn = 0; jn < 2; jn++) {
                        int j = nh * 2 + jn;
                        MMA(acc[mi][j], ah[mi], bh[jn * 2], bh[jn * 2 + 1]);
                        MMA(acc[mi][j], ah[mi], bl[jn * 2], bl[jn * 2 + 1]);
                        MMA(acc[mi][j], al[mi], bh[jn * 2], bh[jn * 2 + 1]);
                    }
                }
            }
        }
    }

    // ---- epilogue ----
    int r0 = wm * 64 + (lane >> 2);
    #pragma unroll
    for (int mi = 0; mi < 4; mi++) {
        int row = r0 + mi * 16;
        float b0 = bsm[row], b1 = bsm[row + 8];
        float* o0 = out + ((size_t)(b * COUT_ + coBase + row)) * HW_;
        float* o1 = o0 + 8 * HW_;
        #pragma unroll
        for (int j = 0; j < 4; j++) {
            int p = pBase + wn * 32 + j * 8 + (lane & 3) * 2;
            if (p < HW_) {
                float2 v0 = make_float2(acc[mi][j][0] + b0, acc[mi][j][1] + b0);
                float2 v1 = make_float2(acc[mi][j][2] + b1, acc[mi][j][3] + b1);
                *(float2*)(o0 + p) = v0;
                *(float2*)(o1 + p) = v1;
            }
        }
    }
}

// ------------------------- launch -------------------------
extern "C" void kernel_launch(void* const* d_in, const int* in_sizes, int n_in,
                              void* d_out, int out_size) {
    const float* x      = (const float*)d_in[0];
    const float* weight = (const float*)d_in[1];
    const float* bias   = (const float*)d_in[2];
    const float* fc1_w  = (const float*)d_in[3];
    const float* fc1_b  = (const float*)d_in[4];
    const float* fc2_w  = (const float*)d_in[5];
    const float* fc2_b  = (const float*)d_in[6];
    float* out = (float*)d_out;

    cudaFuncSetAttribute(conv_kernel,
                         cudaFuncAttributeMaxDynamicSharedMemorySize, DSMEM_BYTES);

    xsplit_kernel<<<(B_ * CIN_ * HW_ / 4) / 256, 256>>>(x);
    pool_kernel<<<dim3(CIN_, B_), 256>>>(x);
    attn_kernel<<<1, 128>>>(fc1_w, fc1_b, fc2_w, fc2_b);
    aggw_kernel<<<dim3(WPE_ / 4 / 256, B_), 256>>>(weight);
    conv_kernel<<<dim3((HW_ + BN - 1) / BN, COUT_ / BM, B_), 256, DSMEM_BYTES>>>(bias, out);
}

// round 5
// speedup vs baseline: 2.6012x; 1.2451x over previous
#include <cuda_runtime.h>
#include <cuda_bf16.h>
#include <cstdint>

#define B_    32
#define CIN_  256
#define COUT_ 256
#define H_    56
#define W_    56
#define HW_   3136
#define KDIM_ 2304
#define WPE_  (COUT_ * CIN_ * 9)

#define BM 128
#define BN 128
#define BK 32
#define NCHUNK 72

// stage layout (32KB)
#define OFF_AH 0
#define OFF_AL 8192
#define OFF_BH 16384
#define OFF_BL 24576
#define STAGE  32768
#define DSMEM_BYTES (3 * STAGE + 1024)

// A tile: 128 rows x 64B; swizzle bits[4:5] ^= bits[7:8]
#define SWA(o) ((o) ^ ((((o) >> 7) & 3) << 4))
// B tile: 32 rows x 256B; swizzle bits[4:6] ^= bits[8:10]
#define SWB(o) ((o) ^ (((o) >> 4) & 0x70))

#define PLANE_N (B_ * CIN_ * HW_)      // 25690112
#define XPAD 128
#define PSTRIDE (PLANE_N + 2 * XPAD)

// ------------------------- scratch -------------------------
__device__ float g_pooled[B_ * CIN_];
__device__ float g_att[B_ * 4];
__device__ __align__(16) __nv_bfloat16 g_awhi[(size_t)B_ * COUT_ * KDIM_];
__device__ __align__(16) __nv_bfloat16 g_awlo[(size_t)B_ * COUT_ * KDIM_];
// 6 planes: [0..2] = hi for kw 0..2 (col-shift -1,0,+1), [3..5] = lo
__device__ __align__(16) __nv_bfloat16 g_xplanes[6][PSTRIDE];

// ------------------------- helpers -------------------------
__device__ __forceinline__ uint32_t smem_u32(const void* p) {
    uint32_t a;
    asm("{ .reg .u64 t; cvta.to.shared.u64 t, %1; cvt.u32.u64 %0, t; }"
        : "=r"(a) : "l"(p));
    return a;
}

__device__ __forceinline__ void split_bf16(float v, unsigned short& h, unsigned short& l) {
    __nv_bfloat16 hb = __float2bfloat16(v);
    float hf = __bfloat162float(hb);
    __nv_bfloat16 lb = __float2bfloat16(v - hf);
    h = __bfloat16_as_ushort(hb);
    l = __bfloat16_as_ushort(lb);
}

#define CP16(dst, src)                                                        \
    asm volatile("cp.async.cg.shared.global [%0], [%1], 16;"                  \
        :: "r"(dst), "l"(src) : "memory")
#define CP_COMMIT() asm volatile("cp.async.commit_group;" ::: "memory")
#define CP_WAIT(n)  asm volatile("cp.async.wait_group %0;" :: "n"(n) : "memory")

#define LDSM4(r, addr)                                                        \
    asm volatile("ldmatrix.sync.aligned.m8n8.x4.shared.b16 {%0,%1,%2,%3}, [%4];" \
        : "=r"((r)[0]), "=r"((r)[1]), "=r"((r)[2]), "=r"((r)[3]) : "r"(addr))

#define LDSM4T(r, addr)                                                       \
    asm volatile("ldmatrix.sync.aligned.m8n8.x4.trans.shared.b16 {%0,%1,%2,%3}, [%4];" \
        : "=r"((r)[0]), "=r"((r)[1]), "=r"((r)[2]), "=r"((r)[3]) : "r"(addr))

#define MMA(d, a, b0v, b1v)                                                   \
    asm volatile("mma.sync.aligned.m16n8k16.row.col.f32.bf16.bf16.f32 "       \
        "{%0,%1,%2,%3}, {%4,%5,%6,%7}, {%8,%9}, {%0,%1,%2,%3};"               \
        : "+f"((d)[0]), "+f"((d)[1]), "+f"((d)[2]), "+f"((d)[3])              \
        : "r"((a)[0]), "r"((a)[1]), "r"((a)[2]), "r"((a)[3]),                 \
          "r"(b0v), "r"(b1v))

// ------------------- kernel 1: x split + shift planes + pool -------------------
// grid (CIN, B), 256 threads. Builds 6 shifted bf16 planes with column-edge
// zeros baked in, and the global average pool.
__global__ void xsplit_kernel(const float* __restrict__ x) {
    __shared__ uint32_t spk[HW_];        // hi | lo<<16 per pixel
    __shared__ float rsm[8];
    int ci = blockIdx.x, b = blockIdx.y;
    int tid = threadIdx.x;
    size_t base = (size_t)(b * CIN_ + ci) * HW_;

    const float4* xr = (const float4*)(x + base);
    float s = 0.f;
    for (int i = tid; i < HW_ / 4; i += 256) {
        float4 v = xr[i];
        float vv[4] = {v.x, v.y, v.z, v.w};
        #pragma unroll
        for (int e = 0; e < 4; e++) {
            unsigned short h, l;
            split_bf16(vv[e], h, l);
            spk[i * 4 + e] = (uint32_t)h | ((uint32_t)l << 16);
            s += vv[e];
        }
    }
    #pragma unroll
    for (int o = 16; o > 0; o >>= 1) s += __shfl_xor_sync(0xffffffffu, s, o);
    if ((tid & 31) == 0) rsm[tid >> 5] = s;
    __syncthreads();
    if (tid == 0) {
        float v = 0.f;
        #pragma unroll
        for (int i = 0; i < 8; i++) v += rsm[i];
        g_pooled[b * CIN_ + ci] = v * (1.f / (float)HW_);
    }

    for (int i = tid; i < HW_; i += 256) {
        int ow = i % W_;
        uint32_t cur = spk[i];
        uint32_t lft = (ow > 0) ? spk[i - 1] : 0u;
        uint32_t rgt = (ow < W_ - 1) ? spk[i + 1] : 0u;
        size_t q = XPAD + base + i;
        g_xplanes[0][q] = __ushort_as_bfloat16((unsigned short)(lft & 0xFFFFu));
        g_xplanes[1][q] = __ushort_as_bfloat16((unsigned short)(cur & 0xFFFFu));
        g_xplanes[2][q] = __ushort_as_bfloat16((unsigned short)(rgt & 0xFFFFu));
        g_xplanes[3][q] = __ushort_as_bfloat16((unsigned short)(lft >> 16));
        g_xplanes[4][q] = __ushort_as_bfloat16((unsigned short)(cur >> 16));
        g_xplanes[5][q] = __ushort_as_bfloat16((unsigned short)(rgt >> 16));
    }
}

// ------------------------- kernel 2: attention -------------------------
__global__ void attn_kernel(const float* __restrict__ fc1_w,
                            const float* __restrict__ fc1_b,
                            const float* __restrict__ fc2_w,
                            const float* __restrict__ fc2_b) {
    __shared__ float a_sm[B_][4];
    __shared__ float l_sm[B_][4];
    int tid = threadIdx.x;
    int b = tid >> 2, k = tid & 3;

    float s = 0.f;
    const float* pb = g_pooled + b * CIN_;
    const float* wk = fc1_w + k * CIN_;
    for (int c = 0; c < CIN_; c++) s += pb[c] * wk[c];
    s += fc1_b[k];
    a_sm[b][k] = fmaxf(s, 0.f);
    __syncthreads();

    float l = fc2_b[k];
    #pragma unroll
    for (int kk = 0; kk < 4; kk++) l += a_sm[b][kk] * fc2_w[k * 4 + kk];
    l_sm[b][k] = l;
    __syncthreads();

    float m = fmaxf(fmaxf(l_sm[b][0], l_sm[b][1]), fmaxf(l_sm[b][2], l_sm[b][3]));
    float e = expf(l_sm[b][k] - m);
    float sum = expf(l_sm[b][0] - m) + expf(l_sm[b][1] - m) +
                expf(l_sm[b][2] - m) + expf(l_sm[b][3] - m);
    g_att[b * 4 + k] = e / sum;
}

// ------------------------- kernel 3: weight agg + split -------------------------
__global__ void aggw_kernel(const float* __restrict__ weight) {
    int b = blockIdx.y;
    int j = blockIdx.x * 256 + threadIdx.x;
    float a0 = g_att[b * 4 + 0], a1 = g_att[b * 4 + 1];
    float a2 = g_att[b * 4 + 2], a3 = g_att[b * 4 + 3];
    const float4* w = (const float4*)weight;
    const int Q = WPE_ / 4;
    float4 w0 = w[0 * Q + j], w1 = w[1 * Q + j], w2 = w[2 * Q + j], w3 = w[3 * Q + j];
    float v[4];
    v[0] = a0 * w0.x + a1 * w1.x + a2 * w2.x + a3 * w3.x;
    v[1] = a0 * w0.y + a1 * w1.y + a2 * w2.y + a3 * w3.y;
    v[2] = a0 * w0.z + a1 * w1.z + a2 * w2.z + a3 * w3.z;
    v[3] = a0 * w0.w + a1 * w1.w + a2 * w2.w + a3 * w3.w;
    uint32_t hi[2], lo[2];
    #pragma unroll
    for (int h = 0; h < 2; h++) {
        unsigned short h0, l0, h1, l1;
        split_bf16(v[h * 2 + 0], h0, l0);
        split_bf16(v[h * 2 + 1], h1, l1);
        hi[h] = (uint32_t)h0 | ((uint32_t)h1 << 16);
        lo[h] = (uint32_t)l0 | ((uint32_t)l1 << 16);
    }
    size_t u = (size_t)b * (WPE_ / 2) + (size_t)j * 2;
    ((uint32_t*)g_awhi)[u]     = hi[0];
    ((uint32_t*)g_awhi)[u + 1] = hi[1];
    ((uint32_t*)g_awlo)[u]     = lo[0];
    ((uint32_t*)g_awlo)[u + 1] = lo[1];
}

// ------------------------- kernel 4: HMMA conv, cp.async 3-stage -------------
__global__ void __launch_bounds__(256, 2)
conv_kernel(const float* __restrict__ bias, float* __restrict__ out) {
    extern __shared__ char dsm[];
    __shared__ float bsm[BM];

    int tid = threadIdx.x, wid = tid >> 5, lane = tid & 31;
    int bx = blockIdx.x;
    int b = blockIdx.z, coBase = blockIdx.y * BM, pBase = bx * BN;
    int wm = wid >> 2, wn = wid & 3;

    uint32_t dbase = smem_u32(dsm);
    uint32_t abase = (dbase + 1023) & ~1023u;

    if (tid < BM) {
        float a0 = g_att[b * 4 + 0], a1 = g_att[b * 4 + 1];
        float a2 = g_att[b * 4 + 2], a3 = g_att[b * 4 + 3];
        int co = coBase + tid;
        bsm[tid] = a0 * bias[0 * COUT_ + co] + a1 * bias[1 * COUT_ + co] +
                   a2 * bias[2 * COUT_ + co] + a3 * bias[3 * COUT_ + co];
    }
    __syncthreads();

    // gmem source bases
    const char* Ahi = (const char*)g_awhi + ((size_t)(b * COUT_ + coBase)) * KDIM_ * 2;
    const char* Alo = (const char*)g_awlo + ((size_t)(b * COUT_ + coBase)) * KDIM_ * 2;
    size_t xoff = XPAD + (size_t)b * CIN_ * HW_;

    // fill thread geometry
    int fa_m = tid & 127, fa_pl = tid >> 7;          // A: row, plane
    const char* fa_src = (fa_pl ? Alo : Ahi) + (size_t)fa_m * (KDIM_ * 2);
    uint32_t fa_doff = (fa_pl ? OFF_AL : OFF_AH);
    int fb_kr = tid >> 3, fb_j0 = (tid & 7) * 2;     // B: k-row, chunk pair

    float acc[4][4][4];
    #pragma unroll
    for (int i = 0; i < 4; i++)
        #pragma unroll
        for (int j = 0; j < 4; j++)
            #pragma unroll
            for (int q = 0; q < 4; q++) acc[i][j][q] = 0.f;

    // ldmatrix raw offsets
    uint32_t rA[4];
    #pragma unroll
    for (int mi = 0; mi < 4; mi++)
        rA[mi] = (uint32_t)((wm * 64 + mi * 16 + (lane & 15)) * 64 + (lane >> 4) * 16);
    uint32_t sB[2];
    {
        int q = lane >> 3, sL = lane & 7;
        #pragma unroll
        for (int nh = 0; nh < 2; nh++)
            sB[nh] = SWB((uint32_t)(((q & 1) * 8 + sL) * 256 +
                                    (wn * 32 + nh * 16 + (q >> 1) * 8) * 2));
    }

    // ---- fill: issue cp.asyncs for chunk c into stage s ----
    auto fill = [&](int s, int c) {
        uint32_t S = abase + s * STAGE;
        int k0 = c * BK;
        // A: this thread's row, 4 x 16B
        {
            const char* src = fa_src + k0 * 2;
            uint32_t db = S + fa_doff;
            #pragma unroll
            for (int j = 0; j < 4; j++)
                CP16(db + SWA((uint32_t)(fa_m * 64 + j * 16)), src + j * 16);
        }
        // B: this thread's k-row, 2 chunks x 2 planes
        {
            int k = k0 + fb_kr;
            int ci = k / 9, rem = k - 9 * ci;
            int kh = rem / 3, kw = rem - 3 * kh;
            size_t e0 = xoff + (size_t)ci * HW_ + (kh - 1) * W_ + pBase;
            const char* sh = (const char*)(g_xplanes[kw]     + e0);
            const char* sl = (const char*)(g_xplanes[kw + 3] + e0);
            #pragma unroll
            for (int jj = 0; jj < 2; jj++) {
                int j = fb_j0 + jj;
                uint32_t off = SWB((uint32_t)(fb_kr * 256 + j * 16));
                CP16(S + OFF_BH + off, sh + j * 16);
                CP16(S + OFF_BL + off, sl + j * 16);
            }
        }
    };

    // ---- patch kh-edge zeros (first/last pixel CTA only), warp-local ----
    auto patch = [&](int s, int c) {
        if (bx != 0 && bx != 24) return;
        uint32_t S = abase + s * STAGE;
        int krow = lane;
        int k = c * BK + krow;
        int ci = k / 9, rem = k - 9 * ci;
        int kh = rem / 3;
        int w0 = wn * 32;
        int lo = 0, hi = 0;
        if (bx == 0 && kh == 0) { lo = w0; hi = min(w0 + 32, 56); }
        if (bx == 24 && kh == 2) { lo = max(w0, 8); hi = min(w0 + 32, 64); }
        for (int pl = lo; pl < hi; pl++) {
            uint32_t off = SWB((uint32_t)(krow * 256 + pl * 2));
            asm volatile("st.shared.u16 [%0], %1;" :: "r"(S + OFF_BH + off),
                         "h"((unsigned short)0) : "memory");
            asm volatile("st.shared.u16 [%0], %1;" :: "r"(S + OFF_BL + off),
                         "h"((unsigned short)0) : "memory");
        }
    };

    // ---- compute chunk in stage s ----
    auto compute = [&](int s) {
        uint32_t S = abase + s * STAGE;
        uint32_t AHs = S + OFF_AH, ALs = S + OFF_AL;
        uint32_t BHs = S + OFF_BH, BLs = S + OFF_BL;
        #pragma unroll
        for (int ks = 0; ks < 2; ks++) {
            uint32_t bh[2][4], bl[2][4];
            #pragma unroll
            for (int nh = 0; nh < 2; nh++) {
                uint32_t offB = sB[nh] + (uint32_t)(ks * 4096);
                LDSM4T(bh[nh], BHs + offB);
                LDSM4T(bl[nh], BLs + offB);
            }
            #pragma unroll
            for (int mi = 0; mi < 4; mi++) {
                uint32_t ah[4], al[4];
                uint32_t offA = SWA(rA[mi] + (uint32_t)(ks * 32));
                LDSM4(ah, AHs + offA);
                LDSM4(al, ALs + offA);
                #pragma unroll
                for (int nh = 0; nh < 2; nh++)
                    #pragma unroll
                    for (int jn = 0; jn < 2; jn++) {
                        int j = nh * 2 + jn;
                        MMA(acc[mi][j], ah, bh[nh][jn * 2], bh[nh][jn * 2 + 1]);
                        MMA(acc[mi][j], ah, bl[nh][jn * 2], bl[nh][jn * 2 + 1]);
                        MMA(acc[mi][j], al, bh[nh][jn * 2], bh[nh][jn * 2 + 1]);
                    }
            }
        }
    };

    // ---- pipeline ----
    fill(0, 0); CP_COMMIT();
    fill(1, 1); CP_COMMIT();

    for (int c = 0; c < NCHUNK; c++) {
        int s = c % 3;
        if (c + 2 < NCHUNK) {
            fill((c + 2) % 3, c + 2); CP_COMMIT();
            CP_WAIT(2);
        } else if (c + 1 < NCHUNK) {
            CP_WAIT(1);
        } else {
            CP_WAIT(0);
        }
        __syncthreads();
        patch(s, c);
        compute(s);
        __syncthreads();
    }

    // ---- epilogue ----
    int r0 = wm * 64 + (lane >> 2);
    #pragma unroll
    for (int mi = 0; mi < 4; mi++) {
        int row = r0 + mi * 16;
        float b0 = bsm[row], b1 = bsm[row + 8];
        float* o0 = out + ((size_t)(b * COUT_ + coBase + row)) * HW_;
        float* o1 = o0 + 8 * HW_;
        #pragma unroll
        for (int j = 0; j < 4; j++) {
            int p = pBase + wn * 32 + j * 8 + (lane & 3) * 2;
            if (p < HW_) {
                float2 v0 = make_float2(acc[mi][j][0] + b0, acc[mi][j][1] + b0);
                float2 v1 = make_float2(acc[mi][j][2] + b1, acc[mi][j][3] + b1);
                *(float2*)(o0 + p) = v0;
                *(float2*)(o1 + p) = v1;
            }
        }
    }
}

// ------------------------- launch -------------------------
extern "C" void kernel_launch(void* const* d_in, const int* in_sizes, int n_in,
                              void* d_out, int out_size) {
    const float* x      = (const float*)d_in[0];
    const float* weight = (const float*)d_in[1];
    const float* bias   = (const float*)d_in[2];
    const float* fc1_w  = (const float*)d_in[3];
    const float* fc1_b  = (const float*)d_in[4];
    const float* fc2_w  = (const float*)d_in[5];
    const float* fc2_b  = (const float*)d_in[6];
    float* out = (float*)d_out;

    cudaFuncSetAttribute(conv_kernel,
                         cudaFuncAttributeMaxDynamicSharedMemorySize, DSMEM_BYTES);

    xsplit_kernel<<<dim3(CIN_, B_), 256>>>(x);
    attn_kernel<<<1, 128>>>(fc1_w, fc1_b, fc2_w, fc2_b);
    aggw_kernel<<<dim3(WPE_ / 4 / 256, B_), 256>>>(weight);
    conv_kernel<<<dim3((HW_ + BN - 1) / BN, COUT_ / BM, B_), 256, DSMEM_BYTES>>>(bias, out);
}